// round 6
// baseline (speedup 1.0000x reference)
#include <cuda_runtime.h>
#include <cuda_bf16.h>
#include <math.h>
#include <stdint.h>

// ---------------------------------------------------------------------------
// Problem constants
// ---------------------------------------------------------------------------
#define BB    32
#define HH    112
#define WW2   112
#define CC    96
#define NHH   3
#define WSS   7
#define SHF   3
#define HIDD  384
#define NTOK  49
#define HDD   32
#define NWIN  8192
#define MTOK  401408

typedef __nv_bfloat16 bf16;
typedef __nv_bfloat162 bf162;

// ---------------------------------------------------------------------------
// Scratch (device globals)
// ---------------------------------------------------------------------------
__device__ __align__(16) bf16  g_ln1h[(size_t)MTOK * CC];
__device__ __align__(16) bf16  g_qh[(size_t)NWIN * NHH * NTOK * HDD];
__device__ __align__(16) bf16  g_kh[(size_t)NWIN * NHH * NTOK * HDD];
__device__ __align__(16) bf16  g_vh[(size_t)NWIN * NHH * NTOK * HDD];
__device__ __align__(16) bf16  g_atth[(size_t)MTOK * CC];
__device__ __align__(16) float g_x1[(size_t)MTOK * CC];
__device__ __align__(16) bf16  g_ln2h[(size_t)MTOK * CC];
__device__ __align__(16) bf16  g_h1h[(size_t)MTOK * HIDD];
__device__ __align__(16) float g_comb[(size_t)256 * NHH * NTOK * NTOK];
__device__ __align__(16) bf16 g_wqkv[288 * 96];
__device__ __align__(16) bf16 g_wproj[96 * 96];
__device__ __align__(16) bf16 g_wfc1[384 * 96];
__device__ __align__(16) bf16 g_wfc2[96 * 384];

__device__ __forceinline__ int rowsrc(int m) {
    int win = m / NTOK, tok = m - win * NTOK;
    int b = win >> 8, widx = win & 255;
    int wh = widx >> 4, ww = widx & 15;
    int r = tok / WSS, c = tok - r * WSS;
    int h = wh * WSS + r + SHF; if (h >= HH) h -= HH;
    int w = ww * WSS + c + SHF; if (w >= WW2) w -= WW2;
    return (b * HH + h) * WW2 + w;
}

// ---------------------------------------------------------------------------
// Weight conversion
// ---------------------------------------------------------------------------
__global__ void __launch_bounds__(256) k_prep(const float* __restrict__ qkvw,
                                              const float* __restrict__ projw,
                                              const float* __restrict__ fc1w,
                                              const float* __restrict__ fc2w) {
    int i = blockIdx.x * 256 + threadIdx.x;
    if (i < 27648)               g_wqkv[i]           = __float2bfloat16(qkvw[i]);
    else if (i < 27648 + 9216)   g_wproj[i - 27648]  = __float2bfloat16(projw[i - 27648]);
    else if (i < 36864 + 36864)  g_wfc1[i - 36864]   = __float2bfloat16(fc1w[i - 36864]);
    else if (i < 110592)         g_wfc2[i - 73728]   = __float2bfloat16(fc2w[i - 73728]);
}

// ---------------------------------------------------------------------------
// LayerNorm (warp per token)
// ---------------------------------------------------------------------------
template <typename OutT>
__device__ __forceinline__ void ln_body(const float* __restrict__ in,
                                        const float* __restrict__ g,
                                        const float* __restrict__ b,
                                        OutT* __restrict__ out, bool gather) {
    int m = blockIdx.x * 8 + (threadIdx.x >> 5);
    int lane = threadIdx.x & 31;
    int src = gather ? rowsrc(m) : m;
    const float* xr = in + (size_t)src * CC;
    float v0 = xr[lane], v1 = xr[lane + 32], v2 = xr[lane + 64];
    float s = v0 + v1 + v2;
#pragma unroll
    for (int o = 16; o > 0; o >>= 1) s += __shfl_xor_sync(0xffffffffu, s, o);
    float mean = s * (1.0f / 96.0f);
    float d0 = v0 - mean, d1 = v1 - mean, d2 = v2 - mean;
    float sq = d0 * d0 + d1 * d1 + d2 * d2;
#pragma unroll
    for (int o = 16; o > 0; o >>= 1) sq += __shfl_xor_sync(0xffffffffu, sq, o);
    float rstd = rsqrtf(sq * (1.0f / 96.0f) + 1e-5f);
    OutT* orow = out + (size_t)m * CC;
    orow[lane]      = (OutT)(d0 * rstd * g[lane]      + b[lane]);
    orow[lane + 32] = (OutT)(d1 * rstd * g[lane + 32] + b[lane + 32]);
    orow[lane + 64] = (OutT)(d2 * rstd * g[lane + 64] + b[lane + 64]);
}

__global__ void __launch_bounds__(256) k_ln1(const float* __restrict__ x,
                                             const float* __restrict__ g,
                                             const float* __restrict__ b) {
    ln_body<bf16>(x, g, b, g_ln1h, true);
}
__global__ void __launch_bounds__(256) k_ln2(const float* __restrict__ g,
                                             const float* __restrict__ b) {
    ln_body<bf16>(g_x1, g, b, g_ln2h, false);
}

// ---------------------------------------------------------------------------
// Combined additive bias
// ---------------------------------------------------------------------------
__global__ void __launch_bounds__(256) k_comb(const float* __restrict__ mask,
                                              const int* __restrict__ ridx,
                                              const float* __restrict__ table) {
    int wh = blockIdx.x;
    int widx = wh / 3, head = wh - widx * 3;
    const int NN = NTOK * NTOK;
    float* dst = g_comb + (size_t)wh * NN;
    const float* msk = mask + (size_t)widx * NN;
    for (int idx = threadIdx.x; idx < NN; idx += 256)
        dst[idx] = msk[idx] + table[ridx[idx] * NHH + head];
}

// ---------------------------------------------------------------------------
// BF16 mma helper
// ---------------------------------------------------------------------------
__device__ __forceinline__ void mma_bf16(float* c, const uint32_t* a, const uint32_t* b) {
    asm volatile(
        "mma.sync.aligned.m16n8k16.row.col.f32.bf16.bf16.f32 "
        "{%0,%1,%2,%3}, {%4,%5,%6,%7}, {%8,%9}, {%0,%1,%2,%3};"
        : "+f"(c[0]), "+f"(c[1]), "+f"(c[2]), "+f"(c[3])
        : "r"(a[0]), "r"(a[1]), "r"(a[2]), "r"(a[3]), "r"(b[0]), "r"(b[1]));
}

// ---------------------------------------------------------------------------
// BF16 tensor-core GEMM: 128x96 tile, BK=96, 8 warps (4m x 2n)
// ---------------------------------------------------------------------------
template <int K, typename Epi>
__device__ __forceinline__ void gemm_body(const bf16* __restrict__ A,
                                          const bf16* __restrict__ W,
                                          Epi epi) {
    constexpr int BK = 96;
    constexpr int KP = 48;
    constexpr int ST = 52;
    __shared__ __align__(16) uint32_t As[128][ST];
    __shared__ __align__(16) uint32_t Bs[96][ST];
    const int tid = threadIdx.x;
    const int wid = tid >> 5, lane = tid & 31;
    const int warp_m = wid >> 1, warp_n = wid & 1;
    const int grp = lane >> 2, qid = lane & 3;
    const int m0 = blockIdx.y * 128;
    const int n0 = blockIdx.x * 96;

    float c[2][6][4];
#pragma unroll
    for (int i = 0; i < 2; i++)
#pragma unroll
        for (int j = 0; j < 6; j++)
#pragma unroll
            for (int e = 0; e < 4; e++) c[i][j][e] = 0.f;

    for (int k0 = 0; k0 < K; k0 += BK) {
#pragma unroll
        for (int i = 0; i < 6; i++) {
            int idx = tid + i * 256;
            int row = idx / 12, c8 = idx - row * 12;
            uint4 v = *reinterpret_cast<const uint4*>(A + (size_t)(m0 + row) * K + k0 + c8 * 8);
            *reinterpret_cast<uint4*>(&As[row][c8 * 4]) = v;
        }
#pragma unroll
        for (int i = 0; i < 5; i++) {
            int idx = tid + i * 256;
            if (idx < 1152) {
                int row = idx / 12, c8 = idx - row * 12;
                uint4 v = *reinterpret_cast<const uint4*>(W + (size_t)(n0 + row) * K + k0 + c8 * 8);
                *reinterpret_cast<uint4*>(&Bs[row][c8 * 4]) = v;
            }
        }
        __syncthreads();

#pragma unroll
        for (int kk = 0; kk < KP; kk += 8) {
            uint32_t a[2][4], b[6][2];
#pragma unroll
            for (int i = 0; i < 2; i++) {
                int ar = warp_m * 32 + i * 16 + grp;
                a[i][0] = As[ar][kk + qid];
                a[i][1] = As[ar + 8][kk + qid];
                a[i][2] = As[ar][kk + qid + 4];
                a[i][3] = As[ar + 8][kk + qid + 4];
            }
#pragma unroll
            for (int j = 0; j < 6; j++) {
                int br = warp_n * 48 + j * 8 + grp;
                b[j][0] = Bs[br][kk + qid];
                b[j][1] = Bs[br][kk + qid + 4];
            }
#pragma unroll
            for (int i = 0; i < 2; i++)
#pragma unroll
                for (int j = 0; j < 6; j++)
                    mma_bf16(c[i][j], a[i], b[j]);
        }
        __syncthreads();
    }

#pragma unroll
    for (int i = 0; i < 2; i++) {
        int r0 = m0 + warp_m * 32 + i * 16 + grp;
#pragma unroll
        for (int j = 0; j < 6; j++) {
            int cn = n0 + warp_n * 48 + j * 8 + qid * 2;
            epi(r0,     cn, c[i][j][0], c[i][j][1]);
            epi(r0 + 8, cn, c[i][j][2], c[i][j][3]);
        }
    }
}

// ------------------------- epilogues ---------------------------------------
struct QkvEpi {
    const float* bias;
    __device__ void operator()(int m, int n, float v0, float v1) const {
        float a = v0 + bias[n], b = v1 + bias[n + 1];
        int which = n / 96; int rem = n - which * 96;
        int head = rem >> 5; int d = rem & 31;
        int win = m / NTOK; int tok = m - win * NTOK;
        size_t off = ((size_t)(win * 3 + head) * NTOK + tok) * HDD + d;
        if (which == 0) {
            a *= 0.17677669529663689f; b *= 0.17677669529663689f;
            *reinterpret_cast<bf162*>(g_qh + off) = __floats2bfloat162_rn(a, b);
        } else if (which == 1) {
            *reinterpret_cast<bf162*>(g_kh + off) = __floats2bfloat162_rn(a, b);
        } else {
            *reinterpret_cast<bf162*>(g_vh + off) = __floats2bfloat162_rn(a, b);
        }
    }
};

struct ProjEpi {
    const float* x;
    const float* pb;
    __device__ void operator()(int m, int n, float v0, float v1) const {
        int src = rowsrc(m);
        size_t o = (size_t)src * CC + n;
        float2 xv = *reinterpret_cast<const float2*>(x + o);
        float2 r = make_float2(xv.x + v0 + pb[n], xv.y + v1 + pb[n + 1]);
        *reinterpret_cast<float2*>(g_x1 + o) = r;
    }
};

struct Fc1Epi {
    const float* fb;
    __device__ void operator()(int m, int n, float v0, float v1) const {
        float a = v0 + fb[n], b = v1 + fb[n + 1];
        a = 0.5f * a * (1.0f + erff(a * 0.70710678118654752f));
        b = 0.5f * b * (1.0f + erff(b * 0.70710678118654752f));
        *reinterpret_cast<bf162*>(g_h1h + (size_t)m * HIDD + n) = __floats2bfloat162_rn(a, b);
    }
};

struct Fc2Epi {
    const float* fb;
    float* out;
    __device__ void operator()(int m, int n, float v0, float v1) const {
        size_t o = (size_t)m * CC + n;
        float2 xv = *reinterpret_cast<const float2*>(g_x1 + o);
        float2 r = make_float2(xv.x + v0 + fb[n], xv.y + v1 + fb[n + 1]);
        *reinterpret_cast<float2*>(out + o) = r;
    }
};

// ------------------------- GEMM wrappers -----------------------------------
__global__ void __launch_bounds__(256) k_gemm_qkv(const float* __restrict__ bias) {
    gemm_body<96>(g_ln1h, g_wqkv, QkvEpi{bias});
}
__global__ void __launch_bounds__(256) k_gemm_proj(const float* __restrict__ pb,
                                                   const float* __restrict__ x) {
    gemm_body<96>(g_atth, g_wproj, ProjEpi{x, pb});
}
__global__ void __launch_bounds__(256) k_gemm_fc1(const float* __restrict__ fb) {
    gemm_body<96>(g_ln2h, g_wfc1, Fc1Epi{fb});
}
__global__ void __launch_bounds__(256) k_gemm_fc2(const float* __restrict__ fb,
                                                  float* __restrict__ out) {
    gemm_body<384>(g_h1h, g_wfc2, Fc2Epi{fb, out});
}

// ---------------------------------------------------------------------------
// Attention via tensor cores: block = (window, head), 128 threads (4 warps)
// S = Q·K^T (64x64x32), softmax (49 rows), O = P·V (64x32x64)
// ---------------------------------------------------------------------------
__global__ void __launch_bounds__(128) k_attn() {
    const int bh = blockIdx.x;
    const int win = bh / 3, head = bh - win * 3;
    const int widx = win & 255;

    __shared__ __align__(16) uint32_t Qs[64][20];   // bf16 pairs, stride 20 words
    __shared__ __align__(16) uint32_t Ks[64][20];
    __shared__ __align__(16) uint32_t Vt[32][36];   // V^T: row d, cols j (pairs)
    __shared__ __align__(16) float    Ss[64][67];   // fp32 scores
    __shared__ __align__(16) bf16     Ps[64][72];   // P bf16 (36-word stride)
    __shared__ float ssum[64];

    const int tid = threadIdx.x;
    const int wid = tid >> 5, lane = tid & 31;
    const int grp = lane >> 2, qid = lane & 3;
    const size_t base = (size_t)bh * (NTOK * HDD);

    // zero P and Vt (padding correctness: padded k-columns contribute exactly 0)
    uint32_t* psw = reinterpret_cast<uint32_t*>(Ps);
    for (int i = tid; i < 64 * 36; i += 128) psw[i] = 0;
    for (int i = tid; i < 32 * 36; i += 128) (&Vt[0][0])[i] = 0;

    // load Q,K: 49 rows x 16 words
    const uint32_t* qg = reinterpret_cast<const uint32_t*>(g_qh + base);
    const uint32_t* kg = reinterpret_cast<const uint32_t*>(g_kh + base);
    for (int idx = tid; idx < 784; idx += 128) {
        int row = idx >> 4, w = idx & 15;
        Qs[row][w] = qg[idx];
        Ks[row][w] = kg[idx];
    }
    // load V transposed: Vt[d][j] = V[j][d]
    const bf16* vg = g_vh + base;
    for (int idx = tid; idx < NTOK * HDD; idx += 128) {
        int j = idx >> 5, d = idx & 31;
        reinterpret_cast<bf16*>(Vt)[d * 72 + j] = vg[idx];
    }
    __syncthreads();

    // ---- S = Q K^T : warp strip m = wid*16, 8 n-tiles, k=32 (2 k16 steps)
    {
        float c[8][4];
#pragma unroll
        for (int j = 0; j < 8; j++)
#pragma unroll
            for (int e = 0; e < 4; e++) c[j][e] = 0.f;
#pragma unroll
        for (int ks = 0; ks < 2; ks++) {
            int kk = ks * 8;
            uint32_t a[4];
            int ar = wid * 16 + grp;
            a[0] = Qs[ar][kk + qid];
            a[1] = Qs[ar + 8][kk + qid];
            a[2] = Qs[ar][kk + qid + 4];
            a[3] = Qs[ar + 8][kk + qid + 4];
#pragma unroll
            for (int jt = 0; jt < 8; jt++) {
                uint32_t b[2];
                int br = jt * 8 + grp;
                b[0] = Ks[br][kk + qid];
                b[1] = Ks[br][kk + qid + 4];
                mma_bf16(c[jt], a, b);
            }
        }
        int r = wid * 16 + grp;
#pragma unroll
        for (int jt = 0; jt < 8; jt++) {
            int col = jt * 8 + qid * 2;
            Ss[r][col]     = c[jt][0];
            Ss[r][col + 1] = c[jt][1];
            Ss[r + 8][col]     = c[jt][2];
            Ss[r + 8][col + 1] = c[jt][3];
        }
    }
    __syncthreads();

    // ---- softmax: thread t owns row t (t < 49); adds comb bias
    if (tid < NTOK) {
        const float* cb = g_comb + (size_t)(widx * 3 + head) * (NTOK * NTOK) + tid * NTOK;
        float mx = -1e30f;
#pragma unroll 7
        for (int j = 0; j < NTOK; j++) {
            float v = Ss[tid][j] + cb[j];
            Ss[tid][j] = v;
            mx = fmaxf(mx, v);
        }
        float sum = 0.f;
#pragma unroll 7
        for (int j = 0; j < NTOK; j++) {
            float e = __expf(Ss[tid][j] - mx);
            sum += e;
            Ps[tid][j] = __float2bfloat16(e);
        }
        ssum[tid] = 1.0f / sum;
    }
    __syncthreads();

    // ---- O = P V : warp strip m = wid*16, 4 n-tiles (d), k=64 (4 k16 steps)
    {
        float o[4][4];
#pragma unroll
        for (int j = 0; j < 4; j++)
#pragma unroll
            for (int e = 0; e < 4; e++) o[j][e] = 0.f;
#pragma unroll
        for (int ks = 0; ks < 4; ks++) {
            int kk = ks * 8;
            uint32_t a[4];
            int ar = wid * 16 + grp;
            a[0] = psw[ar * 36 + kk + qid];
            a[1] = psw[(ar + 8) * 36 + kk + qid];
            a[2] = psw[ar * 36 + kk + qid + 4];
            a[3] = psw[(ar + 8) * 36 + kk + qid + 4];
#pragma unroll
            for (int dt = 0; dt < 4; dt++) {
                uint32_t b[2];
                int br = dt * 8 + grp;
                b[0] = Vt[br][kk + qid];
                b[1] = Vt[br][kk + qid + 4];
                mma_bf16(o[dt], a, b);
            }
        }
        // epilogue: scale by 1/sum, write bf16 to g_atth
        bf16* op = g_atth + (size_t)win * (NTOK * CC) + head * HDD;
        int r = wid * 16 + grp;
        if (r < NTOK) {
            float inv = ssum[r];
#pragma unroll
            for (int dt = 0; dt < 4; dt++) {
                int d = dt * 8 + qid * 2;
                *reinterpret_cast<bf162*>(op + r * CC + d) =
                    __floats2bfloat162_rn(o[dt][0] * inv, o[dt][1] * inv);
            }
        }
        int r2 = r + 8;
        if (r2 < NTOK) {
            float inv = ssum[r2];
#pragma unroll
            for (int dt = 0; dt < 4; dt++) {
                int d = dt * 8 + qid * 2;
                *reinterpret_cast<bf162*>(op + r2 * CC + d) =
                    __floats2bfloat162_rn(o[dt][2] * inv, o[dt][3] * inv);
            }
        }
    }
}

// ---------------------------------------------------------------------------
// Launch
// ---------------------------------------------------------------------------
extern "C" void kernel_launch(void* const* d_in, const int* in_sizes, int n_in,
                              void* d_out, int out_size) {
    const float* x         = (const float*)d_in[0];
    const float* attn_mask = (const float*)d_in[1];
    const int*   rel_index = (const int*)  d_in[2];
    const float* n1g       = (const float*)d_in[3];
    const float* n1b       = (const float*)d_in[4];
    const float* qkv_w     = (const float*)d_in[5];
    const float* qkv_b     = (const float*)d_in[6];
    const float* proj_w    = (const float*)d_in[7];
    const float* proj_b    = (const float*)d_in[8];
    const float* tbl       = (const float*)d_in[9];
    const float* n2g       = (const float*)d_in[10];
    const float* n2b       = (const float*)d_in[11];
    const float* fc1_w     = (const float*)d_in[12];
    const float* fc1_b     = (const float*)d_in[13];
    const float* fc2_w     = (const float*)d_in[14];
    const float* fc2_b     = (const float*)d_in[15];
    float* out = (float*)d_out;

    k_prep<<<432, 256>>>(qkv_w, proj_w, fc1_w, fc2_w);
    k_ln1 <<<MTOK / 8, 256>>>(x, n1g, n1b);
    k_comb<<<256 * NHH, 256>>>(attn_mask, rel_index, tbl);
    k_gemm_qkv <<<dim3(3, MTOK / 128), 256>>>(qkv_b);
    k_attn<<<NWIN * NHH, 128>>>();
    k_gemm_proj<<<dim3(1, MTOK / 128), 256>>>(proj_b, x);
    k_ln2 <<<MTOK / 8, 256>>>(n2g, n2b);
    k_gemm_fc1 <<<dim3(4, MTOK / 128), 256>>>(fc1_b);
    k_gemm_fc2 <<<dim3(1, MTOK / 128), 256>>>(fc2_b, out);
}

// round 9
// speedup vs baseline: 1.1697x; 1.1697x over previous
#include <cuda_runtime.h>
#include <cuda_bf16.h>
#include <math.h>
#include <stdint.h>

// ---------------------------------------------------------------------------
// Problem constants
// ---------------------------------------------------------------------------
#define BB    32
#define HH    112
#define WW2   112
#define CC    96
#define NHH   3
#define WSS   7
#define SHF   3
#define HIDD  384
#define NTOK  49
#define HDD   32
#define NWIN  8192
#define MTOK  401408

typedef __nv_bfloat16 bf16;
typedef __nv_bfloat162 bf162;

// ---------------------------------------------------------------------------
// Scratch (device globals)
// ---------------------------------------------------------------------------
__device__ __align__(16) bf16  g_ln1h[(size_t)MTOK * CC];
__device__ __align__(16) bf16  g_qh[(size_t)NWIN * NHH * NTOK * HDD];
__device__ __align__(16) bf16  g_kh[(size_t)NWIN * NHH * NTOK * HDD];
__device__ __align__(16) bf16  g_vh[(size_t)NWIN * NHH * NTOK * HDD];
__device__ __align__(16) bf16  g_atth[(size_t)MTOK * CC];
__device__ __align__(16) float g_x1[(size_t)MTOK * CC];
__device__ __align__(16) float g_comb[(size_t)256 * NHH * NTOK * NTOK];
__device__ __align__(16) bf16 g_wqkv[288 * 96];
__device__ __align__(16) bf16 g_wproj[96 * 96];
__device__ __align__(16) bf16 g_wfc1[384 * 96];
__device__ __align__(16) bf16 g_wfc2[96 * 384];

__device__ __forceinline__ int rowsrc(int m) {
    int win = m / NTOK, tok = m - win * NTOK;
    int b = win >> 8, widx = win & 255;
    int wh = widx >> 4, ww = widx & 15;
    int r = tok / WSS, c = tok - r * WSS;
    int h = wh * WSS + r + SHF; if (h >= HH) h -= HH;
    int w = ww * WSS + c + SHF; if (w >= WW2) w -= WW2;
    return (b * HH + h) * WW2 + w;
}

// ---------------------------------------------------------------------------
// Weight conversion
// ---------------------------------------------------------------------------
__global__ void __launch_bounds__(256) k_prep(const float* __restrict__ qkvw,
                                              const float* __restrict__ projw,
                                              const float* __restrict__ fc1w,
                                              const float* __restrict__ fc2w) {
    int i = blockIdx.x * 256 + threadIdx.x;
    if (i < 27648)               g_wqkv[i]           = __float2bfloat16(qkvw[i]);
    else if (i < 27648 + 9216)   g_wproj[i - 27648]  = __float2bfloat16(projw[i - 27648]);
    else if (i < 36864 + 36864)  g_wfc1[i - 36864]   = __float2bfloat16(fc1w[i - 36864]);
    else if (i < 110592)         g_wfc2[i - 73728]   = __float2bfloat16(fc2w[i - 73728]);
}

// ---------------------------------------------------------------------------
// LayerNorm1 (warp per token, gathered)
// ---------------------------------------------------------------------------
__global__ void __launch_bounds__(256) k_ln1(const float* __restrict__ x,
                                             const float* __restrict__ g,
                                             const float* __restrict__ b) {
    int m = blockIdx.x * 8 + (threadIdx.x >> 5);
    int lane = threadIdx.x & 31;
    int src = rowsrc(m);
    const float* xr = x + (size_t)src * CC;
    float v0 = xr[lane], v1 = xr[lane + 32], v2 = xr[lane + 64];
    float s = v0 + v1 + v2;
#pragma unroll
    for (int o = 16; o > 0; o >>= 1) s += __shfl_xor_sync(0xffffffffu, s, o);
    float mean = s * (1.0f / 96.0f);
    float d0 = v0 - mean, d1 = v1 - mean, d2 = v2 - mean;
    float sq = d0 * d0 + d1 * d1 + d2 * d2;
#pragma unroll
    for (int o = 16; o > 0; o >>= 1) sq += __shfl_xor_sync(0xffffffffu, sq, o);
    float rstd = rsqrtf(sq * (1.0f / 96.0f) + 1e-5f);
    bf16* orow = g_ln1h + (size_t)m * CC;
    orow[lane]      = (bf16)(d0 * rstd * g[lane]      + b[lane]);
    orow[lane + 32] = (bf16)(d1 * rstd * g[lane + 32] + b[lane + 32]);
    orow[lane + 64] = (bf16)(d2 * rstd * g[lane + 64] + b[lane + 64]);
}

// ---------------------------------------------------------------------------
// Combined additive bias
// ---------------------------------------------------------------------------
__global__ void __launch_bounds__(256) k_comb(const float* __restrict__ mask,
                                              const int* __restrict__ ridx,
                                              const float* __restrict__ table) {
    int wh = blockIdx.x;
    int widx = wh / 3, head = wh - widx * 3;
    const int NN = NTOK * NTOK;
    float* dst = g_comb + (size_t)wh * NN;
    const float* msk = mask + (size_t)widx * NN;
    for (int idx = threadIdx.x; idx < NN; idx += 256)
        dst[idx] = msk[idx] + table[ridx[idx] * NHH + head];
}

// ---------------------------------------------------------------------------
// BF16 mma helper
// ---------------------------------------------------------------------------
__device__ __forceinline__ void mma_bf16(float* c, const uint32_t* a, const uint32_t* b) {
    asm volatile(
        "mma.sync.aligned.m16n8k16.row.col.f32.bf16.bf16.f32 "
        "{%0,%1,%2,%3}, {%4,%5,%6,%7}, {%8,%9}, {%0,%1,%2,%3};"
        : "+f"(c[0]), "+f"(c[1]), "+f"(c[2]), "+f"(c[3])
        : "r"(a[0]), "r"(a[1]), "r"(a[2]), "r"(a[3]), "r"(b[0]), "r"(b[1]));
}

// ---------------------------------------------------------------------------
// BF16 tensor-core GEMM: 128x96 tile, BK=96, 8 warps (4m x 2n)
// ---------------------------------------------------------------------------
template <int K, typename Epi>
__device__ __forceinline__ void gemm_body(const bf16* __restrict__ A,
                                          const bf16* __restrict__ W,
                                          Epi epi) {
    constexpr int BK = 96;
    constexpr int KP = 48;
    constexpr int ST = 52;
    __shared__ __align__(16) uint32_t As[128][ST];
    __shared__ __align__(16) uint32_t Bs[96][ST];
    const int tid = threadIdx.x;
    const int wid = tid >> 5, lane = tid & 31;
    const int warp_m = wid >> 1, warp_n = wid & 1;
    const int grp = lane >> 2, qid = lane & 3;
    const int m0 = blockIdx.y * 128;
    const int n0 = blockIdx.x * 96;

    float c[2][6][4];
#pragma unroll
    for (int i = 0; i < 2; i++)
#pragma unroll
        for (int j = 0; j < 6; j++)
#pragma unroll
            for (int e = 0; e < 4; e++) c[i][j][e] = 0.f;

    for (int k0 = 0; k0 < K; k0 += BK) {
#pragma unroll
        for (int i = 0; i < 6; i++) {
            int idx = tid + i * 256;
            int row = idx / 12, c8 = idx - row * 12;
            uint4 v = *reinterpret_cast<const uint4*>(A + (size_t)(m0 + row) * K + k0 + c8 * 8);
            *reinterpret_cast<uint4*>(&As[row][c8 * 4]) = v;
        }
#pragma unroll
        for (int i = 0; i < 5; i++) {
            int idx = tid + i * 256;
            if (idx < 1152) {
                int row = idx / 12, c8 = idx - row * 12;
                uint4 v = *reinterpret_cast<const uint4*>(W + (size_t)(n0 + row) * K + k0 + c8 * 8);
                *reinterpret_cast<uint4*>(&Bs[row][c8 * 4]) = v;
            }
        }
        __syncthreads();

#pragma unroll
        for (int kk = 0; kk < KP; kk += 8) {
            uint32_t a[2][4], b[6][2];
#pragma unroll
            for (int i = 0; i < 2; i++) {
                int ar = warp_m * 32 + i * 16 + grp;
                a[i][0] = As[ar][kk + qid];
                a[i][1] = As[ar + 8][kk + qid];
                a[i][2] = As[ar][kk + qid + 4];
                a[i][3] = As[ar + 8][kk + qid + 4];
            }
#pragma unroll
            for (int j = 0; j < 6; j++) {
                int br = warp_n * 48 + j * 8 + grp;
                b[j][0] = Bs[br][kk + qid];
                b[j][1] = Bs[br][kk + qid + 4];
            }
#pragma unroll
            for (int i = 0; i < 2; i++)
#pragma unroll
                for (int j = 0; j < 6; j++)
                    mma_bf16(c[i][j], a[i], b[j]);
        }
        __syncthreads();
    }

#pragma unroll
    for (int i = 0; i < 2; i++) {
        int r0 = m0 + warp_m * 32 + i * 16 + grp;
#pragma unroll
        for (int j = 0; j < 6; j++) {
            int cn = n0 + warp_n * 48 + j * 8 + qid * 2;
            epi(r0,     cn, c[i][j][0], c[i][j][1]);
            epi(r0 + 8, cn, c[i][j][2], c[i][j][3]);
        }
    }
}

// ------------------------- epilogues ---------------------------------------
struct QkvEpi {
    const float* bias;
    __device__ void operator()(int m, int n, float v0, float v1) const {
        float a = v0 + bias[n], b = v1 + bias[n + 1];
        int which = n / 96; int rem = n - which * 96;
        int head = rem >> 5; int d = rem & 31;
        int win = m / NTOK; int tok = m - win * NTOK;
        size_t off = ((size_t)(win * 3 + head) * NTOK + tok) * HDD + d;
        if (which == 0) {
            a *= 0.17677669529663689f; b *= 0.17677669529663689f;
            *reinterpret_cast<bf162*>(g_qh + off) = __floats2bfloat162_rn(a, b);
        } else if (which == 1) {
            *reinterpret_cast<bf162*>(g_kh + off) = __floats2bfloat162_rn(a, b);
        } else {
            *reinterpret_cast<bf162*>(g_vh + off) = __floats2bfloat162_rn(a, b);
        }
    }
};

struct ProjEpi {
    const float* x;
    const float* pb;
    __device__ void operator()(int m, int n, float v0, float v1) const {
        int src = rowsrc(m);
        size_t o = (size_t)src * CC + n;
        float2 xv = *reinterpret_cast<const float2*>(x + o);
        float2 r = make_float2(xv.x + v0 + pb[n], xv.y + v1 + pb[n + 1]);
        *reinterpret_cast<float2*>(g_x1 + o) = r;
    }
};

// ------------------------- GEMM wrappers -----------------------------------
__global__ void __launch_bounds__(256) k_gemm_qkv(const float* __restrict__ bias) {
    gemm_body<96>(g_ln1h, g_wqkv, QkvEpi{bias});
}
__global__ void __launch_bounds__(256) k_gemm_proj(const float* __restrict__ pb,
                                                   const float* __restrict__ x) {
    gemm_body<96>(g_atth, g_wproj, ProjEpi{x, pb});
}

// ---------------------------------------------------------------------------
// Fused MLP: LN2 + fc1 + GELU + fc2 + residual.  64 rows/block, 256 threads.
// smem: As(LN'd) 13.3KB + Hs(hidden chunk) 13.3KB + Bs(weights) 20KB = 46.6KB
// ---------------------------------------------------------------------------
__global__ void __launch_bounds__(256) k_mlp(const float* __restrict__ g,
                                             const float* __restrict__ b,
                                             const float* __restrict__ fb1,
                                             const float* __restrict__ fb2,
                                             float* __restrict__ out) {
    __shared__ __align__(16) uint32_t As[64][52];
    __shared__ __align__(16) uint32_t Hs[64][52];
    __shared__ __align__(16) uint32_t Bs[96][52];
    const int tid = threadIdx.x;
    const int wid = tid >> 5, lane = tid & 31;
    const int warp_m = wid >> 2;            // 0..1 (32 rows each)
    const int warp_n = wid & 3;             // 0..3 (24 cols each)
    const int grp = lane >> 2, qid = lane & 3;
    const int m0 = blockIdx.x * 64;

    // ---- LayerNorm2: warp w handles rows w*8 .. w*8+7 ----
    bf16* asb = reinterpret_cast<bf16*>(As);
    for (int r = wid * 8; r < wid * 8 + 8; r++) {
        const float* xr = g_x1 + (size_t)(m0 + r) * CC;
        float v0 = xr[lane], v1 = xr[lane + 32], v2 = xr[lane + 64];
        float s = v0 + v1 + v2;
#pragma unroll
        for (int o = 16; o > 0; o >>= 1) s += __shfl_xor_sync(0xffffffffu, s, o);
        float mean = s * (1.0f / 96.0f);
        float d0 = v0 - mean, d1 = v1 - mean, d2 = v2 - mean;
        float sq = d0 * d0 + d1 * d1 + d2 * d2;
#pragma unroll
        for (int o = 16; o > 0; o >>= 1) sq += __shfl_xor_sync(0xffffffffu, sq, o);
        float rstd = rsqrtf(sq * (1.0f / 96.0f) + 1e-5f);
        asb[r * 104 + lane]      = (bf16)(d0 * rstd * g[lane]      + b[lane]);
        asb[r * 104 + lane + 32] = (bf16)(d1 * rstd * g[lane + 32] + b[lane + 32]);
        asb[r * 104 + lane + 64] = (bf16)(d2 * rstd * g[lane + 64] + b[lane + 64]);
    }
    __syncthreads();

    float c2[2][3][4];
#pragma unroll
    for (int i = 0; i < 2; i++)
#pragma unroll
        for (int j = 0; j < 3; j++)
#pragma unroll
            for (int e = 0; e < 4; e++) c2[i][j][e] = 0.f;

    for (int hc = 0; hc < 4; hc++) {
        // ---- load fc1 chunk weights (rows hc*96 .. +95) ----
        for (int i = tid; i < 1152; i += 256) {
            int row = i / 12, c8 = i - row * 12;
            *reinterpret_cast<uint4*>(&Bs[row][c8 * 4]) =
                *reinterpret_cast<const uint4*>(g_wfc1 + (size_t)(hc * 96 + row) * 96 + c8 * 8);
        }
        __syncthreads();

        // ---- GEMM1: H = As @ fc1_chunk^T ----
        float c1[2][3][4];
#pragma unroll
        for (int i = 0; i < 2; i++)
#pragma unroll
            for (int j = 0; j < 3; j++)
#pragma unroll
                for (int e = 0; e < 4; e++) c1[i][j][e] = 0.f;
#pragma unroll
        for (int kk = 0; kk < 48; kk += 8) {
            uint32_t a[2][4], bb[3][2];
#pragma unroll
            for (int i = 0; i < 2; i++) {
                int ar = warp_m * 32 + i * 16 + grp;
                a[i][0] = As[ar][kk + qid];
                a[i][1] = As[ar + 8][kk + qid];
                a[i][2] = As[ar][kk + qid + 4];
                a[i][3] = As[ar + 8][kk + qid + 4];
            }
#pragma unroll
            for (int j = 0; j < 3; j++) {
                int br = warp_n * 24 + j * 8 + grp;
                bb[j][0] = Bs[br][kk + qid];
                bb[j][1] = Bs[br][kk + qid + 4];
            }
#pragma unroll
            for (int i = 0; i < 2; i++)
#pragma unroll
                for (int j = 0; j < 3; j++)
                    mma_bf16(c1[i][j], a[i], bb[j]);
        }

        // ---- bias + GELU -> Hs (bf16 pairs) ----
#pragma unroll
        for (int i = 0; i < 2; i++) {
            int r = warp_m * 32 + i * 16 + grp;
#pragma unroll
            for (int j = 0; j < 3; j++) {
                int cw = warp_n * 12 + j * 4 + qid;         // word index
                int n = hc * 96 + cw * 2;
                float b0 = fb1[n], b1 = fb1[n + 1];
                float a0 = c1[i][j][0] + b0, a1 = c1[i][j][1] + b1;
                float a2 = c1[i][j][2] + b0, a3 = c1[i][j][3] + b1;
                a0 = 0.5f * a0 * (1.0f + erff(a0 * 0.70710678118654752f));
                a1 = 0.5f * a1 * (1.0f + erff(a1 * 0.70710678118654752f));
                a2 = 0.5f * a2 * (1.0f + erff(a2 * 0.70710678118654752f));
                a3 = 0.5f * a3 * (1.0f + erff(a3 * 0.70710678118654752f));
                bf162 p0 = __floats2bfloat162_rn(a0, a1);
                bf162 p1 = __floats2bfloat162_rn(a2, a3);
                Hs[r][cw]     = *reinterpret_cast<uint32_t*>(&p0);
                Hs[r + 8][cw] = *reinterpret_cast<uint32_t*>(&p1);
            }
        }
        __syncthreads();     // Bs reads done + Hs writes visible

        // ---- load fc2 chunk weights (k-slice hc*96 of each output row) ----
        for (int i = tid; i < 1152; i += 256) {
            int row = i / 12, c8 = i - row * 12;
            *reinterpret_cast<uint4*>(&Bs[row][c8 * 4]) =
                *reinterpret_cast<const uint4*>(g_wfc2 + (size_t)row * 384 + hc * 96 + c8 * 8);
        }
        __syncthreads();

        // ---- GEMM2: c2 += Hs @ fc2_chunk^T ----
#pragma unroll
        for (int kk = 0; kk < 48; kk += 8) {
            uint32_t a[2][4], bb[3][2];
#pragma unroll
            for (int i = 0; i < 2; i++) {
                int ar = warp_m * 32 + i * 16 + grp;
                a[i][0] = Hs[ar][kk + qid];
                a[i][1] = Hs[ar + 8][kk + qid];
                a[i][2] = Hs[ar][kk + qid + 4];
                a[i][3] = Hs[ar + 8][kk + qid + 4];
            }
#pragma unroll
            for (int j = 0; j < 3; j++) {
                int br = warp_n * 24 + j * 8 + grp;
                bb[j][0] = Bs[br][kk + qid];
                bb[j][1] = Bs[br][kk + qid + 4];
            }
#pragma unroll
            for (int i = 0; i < 2; i++)
#pragma unroll
                for (int j = 0; j < 3; j++)
                    mma_bf16(c2[i][j], a[i], bb[j]);
        }
        __syncthreads();     // before next chunk overwrites Bs/Hs
    }

    // ---- epilogue: out = c2 + fc2_b + x1 ----
#pragma unroll
    for (int i = 0; i < 2; i++) {
        int r = m0 + warp_m * 32 + i * 16 + grp;
#pragma unroll
        for (int j = 0; j < 3; j++) {
            int n = warp_n * 24 + j * 8 + qid * 2;
            size_t o0 = (size_t)r * CC + n;
            size_t o1 = (size_t)(r + 8) * CC + n;
            float2 x0 = *reinterpret_cast<const float2*>(g_x1 + o0);
            float2 x1v = *reinterpret_cast<const float2*>(g_x1 + o1);
            float b0 = fb2[n], b1 = fb2[n + 1];
            *reinterpret_cast<float2*>(out + o0) =
                make_float2(x0.x + c2[i][j][0] + b0, x0.y + c2[i][j][1] + b1);
            *reinterpret_cast<float2*>(out + o1) =
                make_float2(x1v.x + c2[i][j][2] + b0, x1v.y + c2[i][j][3] + b1);
        }
    }
}

// ---------------------------------------------------------------------------
// Attention: one block per (window, head), 64 threads, fp32 math, bf16 I/O
// ---------------------------------------------------------------------------
__global__ void __launch_bounds__(64) k_attn() {
    int bh = blockIdx.x;
    int win = bh / 3, head = bh - win * 3;
    int widx = win & 255;

    __shared__ __align__(16) float Ks[NTOK * 32];
    __shared__ __align__(16) float Vs[NTOK * 32];
    __shared__ __align__(16) float Ps[NTOK * 51];
    __shared__ __align__(16) float Os[NTOK * 33];

    const size_t base = (size_t)bh * (NTOK * HDD);
    const int tid = threadIdx.x;

    const uint4* qp = reinterpret_cast<const uint4*>(g_qh + base);
    const uint4* kp = reinterpret_cast<const uint4*>(g_kh + base);
    const uint4* vp = reinterpret_cast<const uint4*>(g_vh + base);
    for (int idx = tid; idx < 196; idx += 64) {
        int row = idx >> 2, seg = idx & 3;
        uint4 qv = qp[idx], kv = kp[idx], vv = vp[idx];
        const bf162* q2 = reinterpret_cast<const bf162*>(&qv);
        const bf162* k2 = reinterpret_cast<const bf162*>(&kv);
        const bf162* v2 = reinterpret_cast<const bf162*>(&vv);
        float* qd = Os + row * 33 + seg * 8;
        float* kd = Ks + row * 32 + seg * 8;
        float* vd = Vs + row * 32 + seg * 8;
#pragma unroll
        for (int t = 0; t < 4; t++) {
            float2 f;
            f = __bfloat1622float2(q2[t]); qd[2 * t] = f.x; qd[2 * t + 1] = f.y;
            f = __bfloat1622float2(k2[t]); kd[2 * t] = f.x; kd[2 * t + 1] = f.y;
            f = __bfloat1622float2(v2[t]); vd[2 * t] = f.x; vd[2 * t + 1] = f.y;
        }
    }
    const float* cp = g_comb + (size_t)(widx * 3 + head) * (NTOK * NTOK);
    for (int idx = tid; idx < NTOK * NTOK; idx += 64) {
        int i = idx / NTOK, j = idx - i * NTOK;
        Ps[i * 51 + j] = cp[idx];
    }
    __syncthreads();

    int i = tid;
    if (i < NTOK) {
        float q[32];
#pragma unroll
        for (int d = 0; d < 32; d++) q[d] = Os[i * 33 + d];

        float mx = -1e30f;
        for (int j = 0; j < NTOK; j++) {
            float s = Ps[i * 51 + j];
            const float4* kr = reinterpret_cast<const float4*>(Ks + j * 32);
#pragma unroll
            for (int d4 = 0; d4 < 8; d4++) {
                float4 kv = kr[d4];
                s += q[4 * d4] * kv.x + q[4 * d4 + 1] * kv.y
                   + q[4 * d4 + 2] * kv.z + q[4 * d4 + 3] * kv.w;
            }
            Ps[i * 51 + j] = s;
            mx = fmaxf(mx, s);
        }
        float sum = 0.f;
        for (int j = 0; j < NTOK; j++) {
            float e = __expf(Ps[i * 51 + j] - mx);
            Ps[i * 51 + j] = e;
            sum += e;
        }
        float inv = 1.0f / sum;

        float o[32];
#pragma unroll
        for (int d = 0; d < 32; d++) o[d] = 0.f;
        for (int j = 0; j < NTOK; j++) {
            float p = Ps[i * 51 + j];
            const float4* vr = reinterpret_cast<const float4*>(Vs + j * 32);
#pragma unroll
            for (int d4 = 0; d4 < 8; d4++) {
                float4 vv = vr[d4];
                o[4 * d4]     += p * vv.x;
                o[4 * d4 + 1] += p * vv.y;
                o[4 * d4 + 2] += p * vv.z;
                o[4 * d4 + 3] += p * vv.w;
            }
        }
#pragma unroll
        for (int d = 0; d < 32; d++) Os[i * 33 + d] = o[d] * inv;
    }
    __syncthreads();

    bf16* op = g_atth + (size_t)win * (NTOK * CC) + head * HDD;
    for (int idx = tid; idx < NTOK * 16; idx += 64) {
        int i2 = idx >> 4, dp = idx & 15;
        float a = Os[i2 * 33 + dp * 2], b = Os[i2 * 33 + dp * 2 + 1];
        *reinterpret_cast<bf162*>(op + i2 * CC + dp * 2) = __floats2bfloat162_rn(a, b);
    }
}

// ---------------------------------------------------------------------------
// Launch
// ---------------------------------------------------------------------------
extern "C" void kernel_launch(void* const* d_in, const int* in_sizes, int n_in,
                              void* d_out, int out_size) {
    const float* x         = (const float*)d_in[0];
    const float* attn_mask = (const float*)d_in[1];
    const int*   rel_index = (const int*)  d_in[2];
    const float* n1g       = (const float*)d_in[3];
    const float* n1b       = (const float*)d_in[4];
    const float* qkv_w     = (const float*)d_in[5];
    const float* qkv_b     = (const float*)d_in[6];
    const float* proj_w    = (const float*)d_in[7];
    const float* proj_b    = (const float*)d_in[8];
    const float* tbl       = (const float*)d_in[9];
    const float* n2g       = (const float*)d_in[10];
    const float* n2b       = (const float*)d_in[11];
    const float* fc1_w     = (const float*)d_in[12];
    const float* fc1_b     = (const float*)d_in[13];
    const float* fc2_w     = (const float*)d_in[14];
    const float* fc2_b     = (const float*)d_in[15];
    float* out = (float*)d_out;

    k_prep<<<432, 256>>>(qkv_w, proj_w, fc1_w, fc2_w);
    k_ln1 <<<MTOK / 8, 256>>>(x, n1g, n1b);
    k_comb<<<256 * NHH, 256>>>(attn_mask, rel_index, tbl);
    k_gemm_qkv <<<dim3(3, MTOK / 128), 256>>>(qkv_b);
    k_attn<<<NWIN * NHH, 64>>>();
    k_gemm_proj<<<dim3(1, MTOK / 128), 256>>>(proj_b, x);
    k_mlp<<<MTOK / 64, 256>>>(n2g, n2b, fc1_b, fc2_b, out);
}